// round 13
// baseline (speedup 1.0000x reference)
#include <cuda_runtime.h>
#include <cuda_fp16.h>
#include <cstdint>

#define S_LEN 8192
#define HID   1024
#define NH    16
#define DH    64
#define WIN   128
#define CHUNK 128
#define KEYS  384
#define ROWE  72            // fp16 elems per padded row (144 B)
#define ROWB  (ROWE * 2)
#define PLANE (KEYS * ROWB)      // 55296 B
#define SMEM_TOTAL (3 * PLANE)   // 165888 B  (K_hi, K_lo, V)
#define LOG2E 1.4426950408889634f

// ---------- PTX wrappers ----------
__device__ __forceinline__ void ldsm4(uint32_t addr, uint32_t r[4]) {
    asm volatile("ldmatrix.sync.aligned.m8n8.x4.shared.b16 {%0,%1,%2,%3}, [%4];"
        : "=r"(r[0]), "=r"(r[1]), "=r"(r[2]), "=r"(r[3]) : "r"(addr));
}
__device__ __forceinline__ void ldsm4t(uint32_t addr, uint32_t r[4]) {
    asm volatile("ldmatrix.sync.aligned.m8n8.x4.trans.shared.b16 {%0,%1,%2,%3}, [%4];"
        : "=r"(r[0]), "=r"(r[1]), "=r"(r[2]), "=r"(r[3]) : "r"(addr));
}
__device__ __forceinline__ void mma16816h(float* c, const uint32_t* a, uint32_t b0, uint32_t b1) {
    asm volatile("mma.sync.aligned.m16n8k16.row.col.f32.f16.f16.f32 "
        "{%0,%1,%2,%3}, {%4,%5,%6,%7}, {%8,%9}, {%0,%1,%2,%3};"
        : "+f"(c[0]), "+f"(c[1]), "+f"(c[2]), "+f"(c[3])
        : "r"(a[0]), "r"(a[1]), "r"(a[2]), "r"(a[3]), "r"(b0), "r"(b1));
}
__device__ __forceinline__ float ex2(float x) {
    float y; asm("ex2.approx.f32 %0, %1;" : "=f"(y) : "f"(x)); return y;
}
// split two floats into packed-fp16 hi word + residual lo word (x0 in low half)
__device__ __forceinline__ void split_pack_h(float x0, float x1, uint32_t& hi, uint32_t& lo) {
    __half2 h2 = __floats2half2_rn(x0, x1);
    float2  bk = __half22float2(h2);
    __half2 l2 = __floats2half2_rn(x0 - bk.x, x1 - bk.y);
    hi = *reinterpret_cast<uint32_t*>(&h2);
    lo = *reinterpret_cast<uint32_t*>(&l2);
}
__device__ __forceinline__ uint32_t pack_h(float x0, float x1) {
    __half2 h2 = __floats2half2_rn(x0, x1);
    return *reinterpret_cast<uint32_t*>(&h2);
}

extern __shared__ char sm[];

__global__ __launch_bounds__(256, 1)
void swa_mma_kernel(const float* __restrict__ Q, const float* __restrict__ K,
                    const float* __restrict__ V, float* __restrict__ O) {
    const int tid  = threadIdx.x;
    const int warp = tid >> 5;
    const int lane = tid & 31;
    const int g    = lane >> 2;
    const int tt   = lane & 3;
    const int mm   = lane >> 3;
    const int lm7  = lane & 7;

    const int c = blockIdx.x, h = blockIdx.y, b = blockIdx.z;
    const int cb = c * CHUNK;
    const int base = cb - WIN;

    const uint32_t SB   = (uint32_t)__cvta_generic_to_shared(sm);
    const uint32_t K_HI = SB;
    const uint32_t K_LO = SB + PLANE;
    const uint32_t V_PL = SB + 2 * PLANE;

    // ---------------- Q fragments: gmem -> regs, scaled by log2e (split fp16) ----------------
    uint32_t aqh[4][4], aql[4][4];
    {
        const int qrow = cb + warp * 16 + g;
        const float* qp = Q + ((size_t)(b * S_LEN + qrow) * HID) + h * DH;
        #pragma unroll
        for (int kg = 0; kg < 4; kg++) {
            const int col0 = kg * 16 + 2 * tt;
            float2 x0 = *(const float2*)(qp + col0);
            float2 x1 = *(const float2*)(qp + 8 * HID + col0);
            float2 x2 = *(const float2*)(qp + col0 + 8);
            float2 x3 = *(const float2*)(qp + 8 * HID + col0 + 8);
            split_pack_h(x0.x * LOG2E, x0.y * LOG2E, aqh[kg][0], aql[kg][0]);
            split_pack_h(x1.x * LOG2E, x1.y * LOG2E, aqh[kg][1], aql[kg][1]);
            split_pack_h(x2.x * LOG2E, x2.y * LOG2E, aqh[kg][2], aql[kg][2]);
            split_pack_h(x3.x * LOG2E, x3.y * LOG2E, aqh[kg][3], aql[kg][3]);
        }
    }

    // ---------------- Stage K (hi/lo) and V, zero-filled out of range ----------------
    {
        #pragma unroll
        for (int it = 0; it < 24; it++) {
            int j   = tid + it * 256;
            int row = j >> 4;
            int c4  = (j & 15) * 4;
            int key = base + row;
            float4 k4 = make_float4(0.f, 0.f, 0.f, 0.f), v4 = k4;
            if (key >= 0 && key < S_LEN) {
                size_t off = ((size_t)(b * S_LEN + key) * HID) + h * DH + c4;
                k4 = *(const float4*)(K + off);
                v4 = *(const float4*)(V + off);
            }
            int so = row * ROWB + c4 * 2;
            uint32_t h0, l0, h1, l1;
            split_pack_h(k4.x, k4.y, h0, l0);
            split_pack_h(k4.z, k4.w, h1, l1);
            *(uint2*)(sm + so)         = make_uint2(h0, h1);
            *(uint2*)(sm + PLANE + so) = make_uint2(l0, l1);
            *(uint2*)(sm + 2 * PLANE + so) =
                make_uint2(pack_h(v4.x, v4.y), pack_h(v4.z, v4.w));
        }
    }
    __syncthreads();

    // ---------------- Main loop: 9 tiles, 2 independent QK accumulator groups ----------------
    float of[8][4];
    #pragma unroll
    for (int j = 0; j < 8; j++)
        #pragma unroll
        for (int r = 0; r < 4; r++) of[j][r] = 0.f;
    float rs[2] = {0.f, 0.f};
    float mx[2] = {-60000.f, -60000.f};

    const int t0  = warp >> 1;
    const int qa0 = cb + warp * 16;

    #pragma unroll 1
    for (int TI = 0; TI < 9; TI++) {
        const int kloc0 = (t0 + TI) * 32;
        const int kabs  = base + kloc0;

        // ---- QK: SH gets QhKh+QhKl (8-deep), SL gets QlKh (4-deep) ----
        float SH[4][4], SL[4][4];
        #pragma unroll
        for (int j = 0; j < 4; j++)
            #pragma unroll
            for (int r = 0; r < 4; r++) { SH[j][r] = 0.f; SL[j][r] = 0.f; }

        #pragma unroll
        for (int kg = 0; kg < 4; kg++) {
            #pragma unroll
            for (int np = 0; np < 2; np++) {
                int keyrow = kloc0 + np * 16 + (mm >> 1) * 8 + lm7;
                int dim    = kg * 16 + (mm & 1) * 8;
                uint32_t off = (uint32_t)(keyrow * ROWB + dim * 2);
                uint32_t kbh[4], kbl[4];
                ldsm4(K_HI + off, kbh);
                ldsm4(K_LO + off, kbl);
                mma16816h(SH[2*np],   aqh[kg], kbh[0], kbh[1]);
                mma16816h(SL[2*np],   aql[kg], kbh[0], kbh[1]);
                mma16816h(SH[2*np],   aqh[kg], kbl[0], kbl[1]);
                mma16816h(SH[2*np+1], aqh[kg], kbh[2], kbh[3]);
                mma16816h(SL[2*np+1], aql[kg], kbh[2], kbh[3]);
                mma16816h(SH[2*np+1], aqh[kg], kbl[2], kbl[3]);
            }
        }

        // ---- combine groups ----
        #pragma unroll
        for (int j = 0; j < 4; j++)
            #pragma unroll
            for (int r = 0; r < 4; r++) SH[j][r] += SL[j][r];

        // ---- mask (edge tiles only) ----
        const bool edge = (TI == 0) | (TI == 8) | (kabs < 0) | (kabs + 31 >= S_LEN);
        if (edge) {
            #pragma unroll
            for (int j = 0; j < 4; j++) {
                #pragma unroll
                for (int r = 0; r < 4; r++) {
                    int key  = kabs + 8 * j + 2 * tt + (r & 1);
                    int qrow = qa0 + g + ((r >> 1) << 3);
                    bool valid = (key >= 0) && (key < S_LEN) &&
                                 (key >= qrow - WIN) && (key <= qrow + WIN);
                    if (!valid) SH[j][r] = -1e30f;
                }
            }
        }

        // ---- online max (base-2) ----
        float mt0 = fmaxf(fmaxf(SH[0][0], SH[0][1]), fmaxf(SH[1][0], SH[1][1]));
        float mt1 = fmaxf(fmaxf(SH[0][2], SH[0][3]), fmaxf(SH[1][2], SH[1][3]));
        mt0 = fmaxf(mt0, fmaxf(fmaxf(SH[2][0], SH[2][1]), fmaxf(SH[3][0], SH[3][1])));
        mt1 = fmaxf(mt1, fmaxf(fmaxf(SH[2][2], SH[2][3]), fmaxf(SH[3][2], SH[3][3])));
        mt0 = fmaxf(mt0, __shfl_xor_sync(0xffffffffu, mt0, 1));
        mt1 = fmaxf(mt1, __shfl_xor_sync(0xffffffffu, mt1, 1));
        mt0 = fmaxf(mt0, __shfl_xor_sync(0xffffffffu, mt0, 2));
        mt1 = fmaxf(mt1, __shfl_xor_sync(0xffffffffu, mt1, 2));
        const float mn0 = fmaxf(mx[0], mt0), mn1 = fmaxf(mx[1], mt1);
        const float sc0 = ex2(mx[0] - mn0),  sc1 = ex2(mx[1] - mn1);
        mx[0] = mn0; mx[1] = mn1;
        rs[0] *= sc0; rs[1] *= sc1;

        // ---- exp + rowsum ----
        #pragma unroll
        for (int j = 0; j < 4; j++) {
            float e0 = ex2(SH[j][0] - mn0);
            float e1 = ex2(SH[j][1] - mn0);
            float e2 = ex2(SH[j][2] - mn1);
            float e3 = ex2(SH[j][3] - mn1);
            rs[0] += e0 + e1; rs[1] += e2 + e3;
            SH[j][0] = e0; SH[j][1] = e1; SH[j][2] = e2; SH[j][3] = e3;
        }

        // ---- rescale O ----
        #pragma unroll
        for (int j = 0; j < 8; j++) {
            of[j][0] *= sc0; of[j][1] *= sc0;
            of[j][2] *= sc1; of[j][3] *= sc1;
        }

        // ---- P pack + PV (single-term fp16) ----
        uint32_t pah[2][4];
        #pragma unroll
        for (int kg = 0; kg < 2; kg++) {
            pah[kg][0] = pack_h(SH[2*kg][0],   SH[2*kg][1]);
            pah[kg][1] = pack_h(SH[2*kg][2],   SH[2*kg][3]);
            pah[kg][2] = pack_h(SH[2*kg+1][0], SH[2*kg+1][1]);
            pah[kg][3] = pack_h(SH[2*kg+1][2], SH[2*kg+1][3]);
        }
        #pragma unroll
        for (int kg = 0; kg < 2; kg++) {
            #pragma unroll
            for (int jp = 0; jp < 4; jp++) {
                int keyrow = kloc0 + kg * 16 + (mm & 1) * 8 + lm7;
                int dim    = (jp * 2 + (mm >> 1)) * 8;
                uint32_t off = (uint32_t)(keyrow * ROWB + dim * 2);
                uint32_t vb[4];
                ldsm4t(V_PL + off, vb);
                mma16816h(of[2*jp],   pah[kg], vb[0], vb[1]);
                mma16816h(of[2*jp+1], pah[kg], vb[2], vb[3]);
            }
        }
    }

    // ---------------- Epilogue ----------------
    rs[0] += __shfl_xor_sync(0xffffffffu, rs[0], 1);
    rs[0] += __shfl_xor_sync(0xffffffffu, rs[0], 2);
    rs[1] += __shfl_xor_sync(0xffffffffu, rs[1], 1);
    rs[1] += __shfl_xor_sync(0xffffffffu, rs[1], 2);
    const float inv_lo = 1.f / rs[0];
    const float inv_hi = 1.f / rs[1];

    const int q_lo = qa0 + g;
    const int q_hi = q_lo + 8;
    #pragma unroll
    for (int j = 0; j < 8; j++) {
        int col = h * DH + 8 * j + 2 * tt;
        size_t off_lo = ((size_t)(b * S_LEN + q_lo) * HID) + col;
        size_t off_hi = ((size_t)(b * S_LEN + q_hi) * HID) + col;
        *(float2*)(O + off_lo) = make_float2(of[j][0] * inv_lo, of[j][1] * inv_lo);
        *(float2*)(O + off_hi) = make_float2(of[j][2] * inv_hi, of[j][3] * inv_hi);
    }
}

extern "C" void kernel_launch(void* const* d_in, const int* in_sizes, int n_in,
                              void* d_out, int out_size) {
    (void)n_in; (void)out_size;
    const float* Q = (const float*)d_in[0];
    const float* K = (const float*)d_in[1];
    const float* V = (const float*)d_in[2];
    float* O = (float*)d_out;

    int B = in_sizes[0] / (S_LEN * HID);
    cudaFuncSetAttribute(swa_mma_kernel,
                         cudaFuncAttributeMaxDynamicSharedMemorySize, SMEM_TOTAL);
    dim3 grid(S_LEN / CHUNK, NH, B);
    swa_mma_kernel<<<grid, 256, SMEM_TOTAL>>>(Q, K, V, O);
}

// round 14
// speedup vs baseline: 1.0920x; 1.0920x over previous
#include <cuda_runtime.h>
#include <cuda_fp16.h>
#include <cstdint>

#define S_LEN 8192
#define HID   1024
#define NH    16
#define DH    64
#define WIN   128
#define CHUNK 128
#define KEYS  384
#define ROWE  72            // fp16 elems per padded row (144 B)
#define ROWB  (ROWE * 2)
#define PLANE (KEYS * ROWB)      // 55296 B
#define SMEM_TOTAL (3 * PLANE)   // 165888 B  (K_hi, K_lo, V)
#define LOG2E 1.4426950408889634f

// ---------- PTX wrappers ----------
__device__ __forceinline__ void ldsm4(uint32_t addr, uint32_t r[4]) {
    asm volatile("ldmatrix.sync.aligned.m8n8.x4.shared.b16 {%0,%1,%2,%3}, [%4];"
        : "=r"(r[0]), "=r"(r[1]), "=r"(r[2]), "=r"(r[3]) : "r"(addr));
}
__device__ __forceinline__ void ldsm4t(uint32_t addr, uint32_t r[4]) {
    asm volatile("ldmatrix.sync.aligned.m8n8.x4.trans.shared.b16 {%0,%1,%2,%3}, [%4];"
        : "=r"(r[0]), "=r"(r[1]), "=r"(r[2]), "=r"(r[3]) : "r"(addr));
}
__device__ __forceinline__ void mma16816h(float* c, const uint32_t* a, uint32_t b0, uint32_t b1) {
    asm volatile("mma.sync.aligned.m16n8k16.row.col.f32.f16.f16.f32 "
        "{%0,%1,%2,%3}, {%4,%5,%6,%7}, {%8,%9}, {%0,%1,%2,%3};"
        : "+f"(c[0]), "+f"(c[1]), "+f"(c[2]), "+f"(c[3])
        : "r"(a[0]), "r"(a[1]), "r"(a[2]), "r"(a[3]), "r"(b0), "r"(b1));
}
__device__ __forceinline__ float ex2(float x) {
    float y; asm("ex2.approx.f32 %0, %1;" : "=f"(y) : "f"(x)); return y;
}
// split two floats into packed-fp16 hi word + residual lo word (x0 in low half)
__device__ __forceinline__ void split_pack_h(float x0, float x1, uint32_t& hi, uint32_t& lo) {
    __half2 h2 = __floats2half2_rn(x0, x1);
    float2  bk = __half22float2(h2);
    __half2 l2 = __floats2half2_rn(x0 - bk.x, x1 - bk.y);
    hi = *reinterpret_cast<uint32_t*>(&h2);
    lo = *reinterpret_cast<uint32_t*>(&l2);
}
__device__ __forceinline__ uint32_t pack_h(float x0, float x1) {
    __half2 h2 = __floats2half2_rn(x0, x1);
    return *reinterpret_cast<uint32_t*>(&h2);
}

extern __shared__ char sm[];

// ---- half of QK for one tile (TI compile-time after unroll): kg = KG0, KG0+1 ----
#define QK_HALF(S, TI, KG0, ZERO) do {                                          \
    const int kloc0q = (t0 + (TI)) * 32;                                        \
    if (ZERO) {                                                                 \
        _Pragma("unroll")                                                       \
        for (int j = 0; j < 4; j++)                                             \
            _Pragma("unroll")                                                   \
            for (int r = 0; r < 4; r++) S[j][r] = 0.f;                          \
    }                                                                           \
    _Pragma("unroll")                                                           \
    for (int kg = (KG0); kg < (KG0) + 2; kg++) {                                \
        _Pragma("unroll")                                                       \
        for (int np = 0; np < 2; np++) {                                        \
            int keyrow = kloc0q + np * 16 + (mm >> 1) * 8 + lm7;                \
            int dim    = kg * 16 + (mm & 1) * 8;                                \
            uint32_t off = (uint32_t)(keyrow * ROWB + dim * 2);                 \
            uint32_t kbh[4], kbl[4];                                            \
            ldsm4(K_HI + off, kbh);                                             \
            ldsm4(K_LO + off, kbl);                                             \
            mma16816h(S[2*np],   aqh[kg], kbh[0], kbh[1]);                      \
            mma16816h(S[2*np],   aql[kg], kbh[0], kbh[1]);                      \
            mma16816h(S[2*np],   aqh[kg], kbl[0], kbl[1]);                      \
            mma16816h(S[2*np+1], aqh[kg], kbh[2], kbh[3]);                      \
            mma16816h(S[2*np+1], aql[kg], kbh[2], kbh[3]);                      \
            mma16816h(S[2*np+1], aqh[kg], kbl[2], kbl[3]);                      \
        }                                                                       \
    }                                                                           \
} while (0)

// ---- mask + cross-quad max + rescale factors ----
#define SM_MAX(S, TI, MN0, MN1, SC0, SC1) do {                                  \
    const int kabs = base + (t0 + (TI)) * 32;                                   \
    const bool edge = ((TI) == 0) | ((TI) == 8) | (kabs < 0) | (kabs + 31 >= S_LEN); \
    if (edge) {                                                                 \
        _Pragma("unroll")                                                       \
        for (int j = 0; j < 4; j++) {                                           \
            _Pragma("unroll")                                                   \
            for (int r = 0; r < 4; r++) {                                       \
                int key  = kabs + 8 * j + 2 * tt + (r & 1);                     \
                int qrow = qa0 + g + ((r >> 1) << 3);                           \
                bool valid = (key >= 0) && (key < S_LEN) &&                     \
                             (key >= qrow - WIN) && (key <= qrow + WIN);        \
                if (!valid) S[j][r] = -1e30f;                                   \
            }                                                                   \
        }                                                                       \
    }                                                                           \
    float mt0 = fmaxf(fmaxf(S[0][0], S[0][1]), fmaxf(S[1][0], S[1][1]));        \
    float mt1 = fmaxf(fmaxf(S[0][2], S[0][3]), fmaxf(S[1][2], S[1][3]));        \
    mt0 = fmaxf(mt0, fmaxf(fmaxf(S[2][0], S[2][1]), fmaxf(S[3][0], S[3][1]))); \
    mt1 = fmaxf(mt1, fmaxf(fmaxf(S[2][2], S[2][3]), fmaxf(S[3][2], S[3][3]))); \
    mt0 = fmaxf(mt0, __shfl_xor_sync(0xffffffffu, mt0, 1));                     \
    mt1 = fmaxf(mt1, __shfl_xor_sync(0xffffffffu, mt1, 1));                     \
    mt0 = fmaxf(mt0, __shfl_xor_sync(0xffffffffu, mt0, 2));                     \
    mt1 = fmaxf(mt1, __shfl_xor_sync(0xffffffffu, mt1, 2));                     \
    MN0 = fmaxf(mx[0], mt0); MN1 = fmaxf(mx[1], mt1);                           \
    SC0 = ex2(mx[0] - MN0);  SC1 = ex2(mx[1] - MN1);                            \
    mx[0] = MN0; mx[1] = MN1;                                                   \
    rs[0] *= SC0; rs[1] *= SC1;                                                 \
} while (0)

// ---- exp + rowsum + of-rescale + fp16 P pack + PV (16 MMAs) ----
#define SM_EXPPV(S, TI, MN0, MN1, SC0, SC1) do {                                \
    const int kloc0p = (t0 + (TI)) * 32;                                        \
    _Pragma("unroll")                                                           \
    for (int j = 0; j < 4; j++) {                                               \
        float e0 = ex2(S[j][0] - MN0);                                          \
        float e1 = ex2(S[j][1] - MN0);                                          \
        float e2 = ex2(S[j][2] - MN1);                                          \
        float e3 = ex2(S[j][3] - MN1);                                          \
        rs[0] += e0 + e1; rs[1] += e2 + e3;                                     \
        S[j][0] = e0; S[j][1] = e1; S[j][2] = e2; S[j][3] = e3;                 \
    }                                                                           \
    _Pragma("unroll")                                                           \
    for (int j = 0; j < 8; j++) {                                               \
        of[j][0] *= SC0; of[j][1] *= SC0;                                       \
        of[j][2] *= SC1; of[j][3] *= SC1;                                       \
    }                                                                           \
    uint32_t pah[2][4];                                                         \
    _Pragma("unroll")                                                           \
    for (int kg = 0; kg < 2; kg++) {                                            \
        pah[kg][0] = pack_h(S[2*kg][0],   S[2*kg][1]);                          \
        pah[kg][1] = pack_h(S[2*kg][2],   S[2*kg][3]);                          \
        pah[kg][2] = pack_h(S[2*kg+1][0], S[2*kg+1][1]);                        \
        pah[kg][3] = pack_h(S[2*kg+1][2], S[2*kg+1][3]);                        \
    }                                                                           \
    _Pragma("unroll")                                                           \
    for (int kg = 0; kg < 2; kg++) {                                            \
        _Pragma("unroll")                                                       \
        for (int jp = 0; jp < 4; jp++) {                                        \
            int keyrow = kloc0p + kg * 16 + (mm & 1) * 8 + lm7;                 \
            int dim    = (jp * 2 + (mm >> 1)) * 8;                              \
            uint32_t off = (uint32_t)(keyrow * ROWB + dim * 2);                 \
            uint32_t vb[4];                                                     \
            ldsm4t(V_PL + off, vb);                                             \
            mma16816h(of[2*jp],   pah[kg], vb[0], vb[1]);                       \
            mma16816h(of[2*jp+1], pah[kg], vb[2], vb[3]);                       \
        }                                                                       \
    }                                                                           \
} while (0)

__global__ __launch_bounds__(256, 1)
void swa_mma_kernel(const float* __restrict__ Q, const float* __restrict__ K,
                    const float* __restrict__ V, float* __restrict__ O) {
    const int tid  = threadIdx.x;
    const int warp = tid >> 5;
    const int lane = tid & 31;
    const int g    = lane >> 2;
    const int tt   = lane & 3;
    const int mm   = lane >> 3;
    const int lm7  = lane & 7;

    const int c = blockIdx.x, h = blockIdx.y, b = blockIdx.z;
    const int cb = c * CHUNK;
    const int base = cb - WIN;

    const uint32_t SB   = (uint32_t)__cvta_generic_to_shared(sm);
    const uint32_t K_HI = SB;
    const uint32_t K_LO = SB + PLANE;
    const uint32_t V_PL = SB + 2 * PLANE;

    // ---------------- Q fragments: gmem -> regs, scaled by log2e (split fp16) ----------------
    uint32_t aqh[4][4], aql[4][4];
    {
        const int qrow = cb + warp * 16 + g;
        const float* qp = Q + ((size_t)(b * S_LEN + qrow) * HID) + h * DH;
        #pragma unroll
        for (int kg = 0; kg < 4; kg++) {
            const int col0 = kg * 16 + 2 * tt;
            float2 x0 = *(const float2*)(qp + col0);
            float2 x1 = *(const float2*)(qp + 8 * HID + col0);
            float2 x2 = *(const float2*)(qp + col0 + 8);
            float2 x3 = *(const float2*)(qp + 8 * HID + col0 + 8);
            split_pack_h(x0.x * LOG2E, x0.y * LOG2E, aqh[kg][0], aql[kg][0]);
            split_pack_h(x1.x * LOG2E, x1.y * LOG2E, aqh[kg][1], aql[kg][1]);
            split_pack_h(x2.x * LOG2E, x2.y * LOG2E, aqh[kg][2], aql[kg][2]);
            split_pack_h(x3.x * LOG2E, x3.y * LOG2E, aqh[kg][3], aql[kg][3]);
        }
    }

    // ---------------- Stage K (hi/lo) and V, zero-filled out of range ----------------
    {
        #pragma unroll
        for (int it = 0; it < 24; it++) {
            int j   = tid + it * 256;
            int row = j >> 4;
            int c4  = (j & 15) * 4;
            int key = base + row;
            float4 k4 = make_float4(0.f, 0.f, 0.f, 0.f), v4 = k4;
            if (key >= 0 && key < S_LEN) {
                size_t off = ((size_t)(b * S_LEN + key) * HID) + h * DH + c4;
                k4 = *(const float4*)(K + off);
                v4 = *(const float4*)(V + off);
            }
            int so = row * ROWB + c4 * 2;
            uint32_t h0, l0, h1, l1;
            split_pack_h(k4.x, k4.y, h0, l0);
            split_pack_h(k4.z, k4.w, h1, l1);
            *(uint2*)(sm + so)         = make_uint2(h0, h1);
            *(uint2*)(sm + PLANE + so) = make_uint2(l0, l1);
            *(uint2*)(sm + 2 * PLANE + so) =
                make_uint2(pack_h(v4.x, v4.y), pack_h(v4.z, v4.w));
        }
    }
    __syncthreads();

    // ---------------- Main loop: FULLY UNROLLED 9 tiles, A/B bracketed ----------------
    float of[8][4];
    #pragma unroll
    for (int j = 0; j < 8; j++)
        #pragma unroll
        for (int r = 0; r < 4; r++) of[j][r] = 0.f;
    float rs[2] = {0.f, 0.f};
    float mx[2] = {-60000.f, -60000.f};

    const int t0  = warp >> 1;
    const int qa0 = cb + warp * 16;

    float sA[4][4], sB[4][4];
    float mn0, mn1, sc0, sc1;

    QK_HALF(sA, 0, 0, true);
    QK_HALF(sA, 0, 2, false);
    #pragma unroll
    for (int ii = 0; ii < 4; ii++) {
        // tile 2ii+1 QK brackets tile 2ii softmax stages
        QK_HALF(sB, 2 * ii + 1, 0, true);
        SM_MAX(sA, 2 * ii, mn0, mn1, sc0, sc1);
        QK_HALF(sB, 2 * ii + 1, 2, false);
        SM_EXPPV(sA, 2 * ii, mn0, mn1, sc0, sc1);
        // tile 2ii+2 QK brackets tile 2ii+1 softmax stages
        QK_HALF(sA, 2 * ii + 2, 0, true);
        SM_MAX(sB, 2 * ii + 1, mn0, mn1, sc0, sc1);
        QK_HALF(sA, 2 * ii + 2, 2, false);
        SM_EXPPV(sB, 2 * ii + 1, mn0, mn1, sc0, sc1);
    }
    SM_MAX(sA, 8, mn0, mn1, sc0, sc1);
    SM_EXPPV(sA, 8, mn0, mn1, sc0, sc1);

    // ---------------- Epilogue ----------------
    rs[0] += __shfl_xor_sync(0xffffffffu, rs[0], 1);
    rs[0] += __shfl_xor_sync(0xffffffffu, rs[0], 2);
    rs[1] += __shfl_xor_sync(0xffffffffu, rs[1], 1);
    rs[1] += __shfl_xor_sync(0xffffffffu, rs[1], 2);
    const float inv_lo = 1.f / rs[0];
    const float inv_hi = 1.f / rs[1];

    const int q_lo = qa0 + g;
    const int q_hi = q_lo + 8;
    #pragma unroll
    for (int j = 0; j < 8; j++) {
        int col = h * DH + 8 * j + 2 * tt;
        size_t off_lo = ((size_t)(b * S_LEN + q_lo) * HID) + col;
        size_t off_hi = ((size_t)(b * S_LEN + q_hi) * HID) + col;
        *(float2*)(O + off_lo) = make_float2(of[j][0] * inv_lo, of[j][1] * inv_lo);
        *(float2*)(O + off_hi) = make_float2(of[j][2] * inv_hi, of[j][3] * inv_hi);
    }
}

extern "C" void kernel_launch(void* const* d_in, const int* in_sizes, int n_in,
                              void* d_out, int out_size) {
    (void)n_in; (void)out_size;
    const float* Q = (const float*)d_in[0];
    const float* K = (const float*)d_in[1];
    const float* V = (const float*)d_in[2];
    float* O = (float*)d_out;

    int B = in_sizes[0] / (S_LEN * HID);
    cudaFuncSetAttribute(swa_mma_kernel,
                         cudaFuncAttributeMaxDynamicSharedMemorySize, SMEM_TOTAL);
    dim3 grid(S_LEN / CHUNK, NH, B);
    swa_mma_kernel<<<grid, 256, SMEM_TOTAL>>>(Q, K, V, O);
}